// round 2
// baseline (speedup 1.0000x reference)
#include <cuda_runtime.h>
#include <cstdint>

// ---------------------------------------------------------------------------
// TrajectoryFK on GB300: parallel affine scan + unrolled kinematic tree.
//
// element e_t = (M_t, u_t), M_t = rotmat(joint1 6d), u_t = M_t @ vel_t
// combine(a earlier, b later) = (a.M @ b.M, a.u + a.M @ b.u)   (associative)
// inclusive prefix -> (R_t, root_pos_t)
// ---------------------------------------------------------------------------

constexpr int L       = 65536;
constexpr int ROWF    = 132;      // floats per timestep in pred_series (22*6)
constexpr int ABLK    = 256;      // steps per scan block
constexpr int NBLKA   = L / ABLK; // 256
constexpr int CTHR    = 128;
constexpr int NBLKC   = L / CTHR; // 512
constexpr int SOSTR   = 129;      // smem out stride (conflict-free)

__device__ float g_scratch[12 * L];     // block-local inclusive (SoA: comp*L + t)
__device__ float g_agg[NBLKA * 12];     // per-block aggregates
__device__ float g_pref[NBLKA * 12];    // exclusive block prefixes

// 6D continuous -> 3x3 rotation (row-major, columns are b1,b2,b3)
__device__ __forceinline__ void d6_to_mat(const float* d, float* m) {
    float a1x = d[0], a1y = d[1], a1z = d[2];
    float a2x = d[3], a2y = d[4], a2z = d[5];
    float n1 = a1x * a1x + a1y * a1y + a1z * a1z;
    float i1 = rsqrtf(fmaxf(n1, 1e-24f));
    float b1x = a1x * i1, b1y = a1y * i1, b1z = a1z * i1;
    float dp = b1x * a2x + b1y * a2y + b1z * a2z;
    float c2x = a2x - b1x * dp, c2y = a2y - b1y * dp, c2z = a2z - b1z * dp;
    float n2 = c2x * c2x + c2y * c2y + c2z * c2z;
    float i2 = rsqrtf(fmaxf(n2, 1e-24f));
    float b2x = c2x * i2, b2y = c2y * i2, b2z = c2z * i2;
    float b3x = b1y * b2z - b1z * b2y;
    float b3y = b1z * b2x - b1x * b2z;
    float b3z = b1x * b2y - b1y * b2x;
    m[0] = b1x; m[1] = b2x; m[2] = b3x;
    m[3] = b1y; m[4] = b2y; m[5] = b3y;
    m[6] = b1z; m[7] = b2z; m[8] = b3z;
}

// c = a @ b, 3x3 row-major (c must not alias a or b)
__device__ __forceinline__ void mat3mul(float* __restrict__ c,
                                        const float* a, const float* b) {
#pragma unroll
    for (int r = 0; r < 3; r++) {
        float a0 = a[r * 3], a1 = a[r * 3 + 1], a2 = a[r * 3 + 2];
#pragma unroll
        for (int k = 0; k < 3; k++)
            c[r * 3 + k] = a0 * b[k] + a1 * b[3 + k] + a2 * b[6 + k];
    }
}

// r = a ∘ b (a earlier). 12-float affine: [0..8]=M rowmajor, [9..11]=u.
// Alias-safe via temp.
__device__ __forceinline__ void aff_combine(float* r, const float* a, const float* b) {
    float t[12];
#pragma unroll
    for (int rr = 0; rr < 3; rr++) {
        float a0 = a[rr * 3], a1 = a[rr * 3 + 1], a2 = a[rr * 3 + 2];
#pragma unroll
        for (int k = 0; k < 3; k++)
            t[rr * 3 + k] = a0 * b[k] + a1 * b[3 + k] + a2 * b[6 + k];
        t[9 + rr] = a[9 + rr] + a0 * b[9] + a1 * b[10] + a2 * b[11];
    }
#pragma unroll
    for (int i = 0; i < 12; i++) r[i] = t[i];
}

__device__ __forceinline__ void aff_identity(float* v) {
#pragma unroll
    for (int i = 0; i < 12; i++) v[i] = 0.0f;
    v[0] = v[4] = v[8] = 1.0f;
}

// ---------------------------------------------------------------------------
// Kernel A: per-block inclusive scan of affine elements.
// ---------------------------------------------------------------------------
__global__ void __launch_bounds__(ABLK)
kernelA(const float* __restrict__ pred) {
    int t = blockIdx.x * ABLK + threadIdx.x;
    const float* row = pred + (size_t)t * ROWF;

    float2 v01 = *(const float2*)(row);
    float  vz  = row[2];
    float2 e0 = *(const float2*)(row + 6);
    float2 e1 = *(const float2*)(row + 8);
    float2 e2 = *(const float2*)(row + 10);
    float d6[6] = {e0.x, e0.y, e1.x, e1.y, e2.x, e2.y};

    float val[12];
    d6_to_mat(d6, val);
    float vx = v01.x, vy = v01.y;
    val[9]  = val[0] * vx + val[1] * vy + val[2] * vz;
    val[10] = val[3] * vx + val[4] * vy + val[5] * vz;
    val[11] = val[6] * vx + val[7] * vy + val[8] * vz;

    int lane = threadIdx.x & 31, warp = threadIdx.x >> 5;

    // warp inclusive scan (non-commutative, order-preserving)
#pragma unroll
    for (int off = 1; off < 32; off <<= 1) {
        float o[12];
#pragma unroll
        for (int i = 0; i < 12; i++)
            o[i] = __shfl_up_sync(0xffffffffu, val[i], off);
        if (lane >= off) aff_combine(val, o, val);
    }

    __shared__ float s_wagg[8][12];
    if (lane == 31) {
#pragma unroll
        for (int i = 0; i < 12; i++) s_wagg[warp][i] = val[i];
    }
    __syncthreads();

    float pre[12];
    aff_identity(pre);
    for (int w = 0; w < warp; w++) aff_combine(pre, pre, s_wagg[w]);

    float inc[12];
    aff_combine(inc, pre, val);

#pragma unroll
    for (int i = 0; i < 12; i++) g_scratch[i * L + t] = inc[i];

    if (threadIdx.x == ABLK - 1) {
#pragma unroll
        for (int i = 0; i < 12; i++) g_agg[blockIdx.x * 12 + i] = inc[i];
    }
}

// ---------------------------------------------------------------------------
// Kernel B: scan 256 block aggregates -> exclusive prefixes.
// ---------------------------------------------------------------------------
__global__ void __launch_bounds__(NBLKA)
kernelB() {
    int tid = threadIdx.x, lane = tid & 31, warp = tid >> 5;
    float val[12];
#pragma unroll
    for (int i = 0; i < 12; i++) val[i] = g_agg[tid * 12 + i];

#pragma unroll
    for (int off = 1; off < 32; off <<= 1) {
        float o[12];
#pragma unroll
        for (int i = 0; i < 12; i++)
            o[i] = __shfl_up_sync(0xffffffffu, val[i], off);
        if (lane >= off) aff_combine(val, o, val);
    }

    __shared__ float s_wagg[8][12];
    if (lane == 31) {
#pragma unroll
        for (int i = 0; i < 12; i++) s_wagg[warp][i] = val[i];
    }
    __syncthreads();

    float pre[12];
    aff_identity(pre);
    for (int w = 0; w < warp; w++) aff_combine(pre, pre, s_wagg[w]);

    float inc[12];
    aff_combine(inc, pre, val);

    if (tid == 0) {
        float id[12];
        aff_identity(id);
#pragma unroll
        for (int i = 0; i < 12; i++) g_pref[i] = id[i];
    }
    if (tid < NBLKA - 1) {
#pragma unroll
        for (int i = 0; i < 12; i++) g_pref[(tid + 1) * 12 + i] = inc[i];
    }
}

// ---------------------------------------------------------------------------
// Kernel C: apply carry, run unrolled FK tree, coalesced output.
// ---------------------------------------------------------------------------
__device__ __forceinline__ void fk_rot(float* Rc, const float* Rp,
                                       const float* row, int j) {
    float2 e0 = *(const float2*)(row + j * 6);
    float2 e1 = *(const float2*)(row + j * 6 + 2);
    float2 e2 = *(const float2*)(row + j * 6 + 4);
    float d6[6] = {e0.x, e0.y, e1.x, e1.y, e2.x, e2.y};
    float M[9];
    d6_to_mat(d6, M);
    mat3mul(Rc, Rp, M);
}

__device__ __forceinline__ void fk_pos(float* pc, const float* pp, const float* Rp,
                                       const float* s_off, int j) {
    float ox = s_off[j * 3], oy = s_off[j * 3 + 1], oz = s_off[j * 3 + 2];
    pc[0] = pp[0] + Rp[0] * ox + Rp[1] * oy + Rp[2] * oz;
    pc[1] = pp[1] + Rp[3] * ox + Rp[4] * oy + Rp[5] * oz;
    pc[2] = pp[2] + Rp[6] * ox + Rp[7] * oy + Rp[8] * oz;
}

__device__ __forceinline__ void emit(float* s_out, int tid, int j, const float* p) {
    s_out[(j * 3 + 0) * SOSTR + tid] = p[0];
    s_out[(j * 3 + 1) * SOSTR + tid] = p[1];
    s_out[(j * 3 + 2) * SOSTR + tid] = p[2];
}

__global__ void __launch_bounds__(CTHR)
kernelC(const float* __restrict__ pred, const float* __restrict__ offs,
        float* __restrict__ out) {
    __shared__ float s_out[66 * SOSTR];
    __shared__ float s_off[66];
    int tid = threadIdx.x;
    size_t base = (size_t)blockIdx.x * CTHR;

    if (tid < 66) s_off[tid] = offs[tid];
    __syncthreads();

    int t = (int)base + tid;
    const float* row = pred + (size_t)t * ROWF;

    // global inclusive = blockPrefix ∘ local
    int ab = t >> 8;
    float P[12], Lv[12], G[12];
#pragma unroll
    for (int i = 0; i < 12; i++) P[i] = g_pref[ab * 12 + i];
#pragma unroll
    for (int i = 0; i < 12; i++) Lv[i] = g_scratch[i * L + t];
    aff_combine(G, P, Lv);

    const float* R = G;                       // R_t (root & joint1 rotation)
    float pos0[3] = {G[9], G[10], G[11]};     // root_pos_t
    emit(s_out, tid, 0, pos0);

    float pos1[3]; fk_pos(pos1, pos0, R, s_off, 1);  emit(s_out, tid, 1, pos1);

    // chain 1 -> 4 -> 7 -> 10
    float R4[9];  fk_rot(R4, R, row, 4);
    float pos4[3];  fk_pos(pos4, pos1, R, s_off, 4);   emit(s_out, tid, 4, pos4);
    float R7[9];  fk_rot(R7, R4, row, 7);
    float pos7[3];  fk_pos(pos7, pos4, R4, s_off, 7);  emit(s_out, tid, 7, pos7);
    float pos10[3]; fk_pos(pos10, pos7, R7, s_off, 10); emit(s_out, tid, 10, pos10);

    // chain 0 -> 2 -> 5 -> 8 -> 11
    float R2[9];  fk_rot(R2, R, row, 2);
    float pos2[3];  fk_pos(pos2, pos0, R, s_off, 2);   emit(s_out, tid, 2, pos2);
    float R5[9];  fk_rot(R5, R2, row, 5);
    float pos5[3];  fk_pos(pos5, pos2, R2, s_off, 5);  emit(s_out, tid, 5, pos5);
    float R8[9];  fk_rot(R8, R5, row, 8);
    float pos8[3];  fk_pos(pos8, pos5, R5, s_off, 8);  emit(s_out, tid, 8, pos8);
    float pos11[3]; fk_pos(pos11, pos8, R8, s_off, 11); emit(s_out, tid, 11, pos11);

    // chain 0 -> 3 -> 6 -> 9
    float R3[9];  fk_rot(R3, R, row, 3);
    float pos3[3];  fk_pos(pos3, pos0, R, s_off, 3);   emit(s_out, tid, 3, pos3);
    float R6[9];  fk_rot(R6, R3, row, 6);
    float pos6[3];  fk_pos(pos6, pos3, R3, s_off, 6);  emit(s_out, tid, 6, pos6);
    float R9[9];  fk_rot(R9, R6, row, 9);
    float pos9[3];  fk_pos(pos9, pos6, R6, s_off, 9);  emit(s_out, tid, 9, pos9);

    // 9 -> 12 -> 15
    float R12[9]; fk_rot(R12, R9, row, 12);
    float pos12[3]; fk_pos(pos12, pos9, R9, s_off, 12); emit(s_out, tid, 12, pos12);
    float pos15[3]; fk_pos(pos15, pos12, R12, s_off, 15); emit(s_out, tid, 15, pos15);

    // 9 -> 13 -> 16 -> 18 -> 20
    float R13[9]; fk_rot(R13, R9, row, 13);
    float pos13[3]; fk_pos(pos13, pos9, R9, s_off, 13); emit(s_out, tid, 13, pos13);
    float R16[9]; fk_rot(R16, R13, row, 16);
    float pos16[3]; fk_pos(pos16, pos13, R13, s_off, 16); emit(s_out, tid, 16, pos16);
    float R18[9]; fk_rot(R18, R16, row, 18);
    float pos18[3]; fk_pos(pos18, pos16, R16, s_off, 18); emit(s_out, tid, 18, pos18);
    float pos20[3]; fk_pos(pos20, pos18, R18, s_off, 20); emit(s_out, tid, 20, pos20);

    // 9 -> 14 -> 17 -> 19 -> 21
    float R14[9]; fk_rot(R14, R9, row, 14);
    float pos14[3]; fk_pos(pos14, pos9, R9, s_off, 14); emit(s_out, tid, 14, pos14);
    float R17[9]; fk_rot(R17, R14, row, 17);
    float pos17[3]; fk_pos(pos17, pos14, R14, s_off, 17); emit(s_out, tid, 17, pos17);
    float R19[9]; fk_rot(R19, R17, row, 19);
    float pos19[3]; fk_pos(pos19, pos17, R17, s_off, 19); emit(s_out, tid, 19, pos19);
    float pos21[3]; fk_pos(pos21, pos19, R19, s_off, 21); emit(s_out, tid, 21, pos21);

    __syncthreads();

    // coalesced write: out[t*66 + c] = s_out[c*SOSTR + t_local]
    float* o = out + base * 66;
    for (int i = tid; i < CTHR * 66; i += CTHR) {
        int rr = i / 66;
        int cc = i - rr * 66;
        o[i] = s_out[cc * SOSTR + rr];
    }
}

// ---------------------------------------------------------------------------
extern "C" void kernel_launch(void* const* d_in, const int* in_sizes, int n_in,
                              void* d_out, int out_size) {
    const float* pred = (const float*)d_in[0];   // (65536, 22, 6) f32
    const float* offs = (const float*)d_in[1];   // (22, 3) f32
    float* out = (float*)d_out;                  // (65536, 22, 3) f32

    kernelA<<<NBLKA, ABLK>>>(pred);
    kernelB<<<1, NBLKA>>>();
    kernelC<<<NBLKC, CTHR>>>(pred, offs, out);
}